// round 6
// baseline (speedup 1.0000x reference)
#include <cuda_runtime.h>
#include <cuda_bf16.h>
#include <math.h>

#define N_FFT 16000
#define BATCH 512
#define IN_DIM 2048
#define NTH 512

// ---------------- scratch (static __device__, no allocation) ----------------
__device__ int    g_h[2 * IN_DIM];
__device__ float  g_s[2 * IN_DIM];
__device__ float2 g_tw[N_FFT];      // W_N^j = exp(-2*pi*i*j/N)
__device__ int    g_sig[N_FFT];     // scrambled position -> natural frequency
__device__ int    g_isig[N_FFT];    // natural frequency -> scrambled position
__device__ __align__(16) float g_norm[N_FFT];  // per-column sum of squares

// ---------------- complex helpers ----------------
__device__ __forceinline__ float2 cmul(float2 a, float2 b) {
    return make_float2(a.x * b.x - a.y * b.y, a.x * b.y + a.y * b.x);
}
__device__ __forceinline__ float2 cmulc(float2 a, float2 b) {  // a * conj(b)
    return make_float2(a.x * b.x + a.y * b.y, a.y * b.x - a.x * b.y);
}
__device__ __forceinline__ float2 cadd(float2 a, float2 b) {
    return make_float2(a.x + b.x, a.y + b.y);
}
__device__ __forceinline__ float2 csub(float2 a, float2 b) {
    return make_float2(a.x - b.x, a.y - b.y);
}
__device__ __forceinline__ float2 mul_negi(float2 a) { return make_float2(a.y, -a.x); }
__device__ __forceinline__ float2 mul_posi(float2 a) { return make_float2(-a.y, a.x); }

// W5^j
__constant__ float2 W5c[5] = {
    { 1.0f,                  0.0f                 },
    { 0.30901699437494742f, -0.95105651629515357f },
    {-0.80901699437494742f, -0.58778525229247314f },
    {-0.80901699437494745f,  0.58778525229247312f },
    { 0.30901699437494740f,  0.95105651629515364f }
};
// W10^m, m=0..4
__constant__ float2 W10c[5] = {
    { 1.0f,                  0.0f                 },
    { 0.80901699437494742f, -0.58778525229247312f },
    { 0.30901699437494742f, -0.95105651629515357f },
    {-0.30901699437494742f, -0.95105651629515357f },
    {-0.80901699437494742f, -0.58778525229247312f }
};
// W20^m, m=0..9
__constant__ float2 W20c[10] = {
    { 1.0f,                  0.0f                 },
    { 0.95105651629515353f, -0.30901699437494742f },
    { 0.80901699437494745f, -0.58778525229247312f },
    { 0.58778525229247312f, -0.80901699437494745f },
    { 0.30901699437494742f, -0.95105651629515353f },
    { 0.0f,                 -1.0f                 },
    {-0.30901699437494742f, -0.95105651629515353f },
    {-0.58778525229247312f, -0.80901699437494745f },
    {-0.80901699437494745f, -0.58778525229247312f },
    {-0.95105651629515353f, -0.30901699437494742f }
};
// W25^j, j=0..16 (max needed index b*c = 16)
__constant__ float2 W25c[17] = {
    { 1.0f,                  0.0f                 },
    { 0.96858316112863108f, -0.24868988716485479f },
    { 0.87630668004386358f, -0.48175367410171532f },
    { 0.72896862742141155f, -0.68454710592868867f },
    { 0.53582679497899666f, -0.84432792550201508f },
    { 0.30901699437494742f, -0.95105651629515357f },
    { 0.06279051952931337f, -0.99802672842827156f },
    {-0.18738131458572463f, -0.98228725072868872f },
    {-0.42577929156507266f, -0.90482705246601958f },
    {-0.63742398974868971f, -0.77051324277578925f },
    {-0.80901699437494745f, -0.58778525229247312f },
    {-0.92977648588825146f, -0.36812455268467797f },
    {-0.99211470131447788f, -0.12533323356430426f },
    {-0.99211470131447788f,  0.12533323356430426f },
    {-0.92977648588825146f,  0.36812455268467797f },
    {-0.80901699437494745f,  0.58778525229247312f },
    {-0.63742398974868971f,  0.77051324277578925f }
};
// W32^m, m=0..15
__constant__ float2 W32c[16] = {
    { 1.0f,                  0.0f                 },
    { 0.98078528040323044f, -0.19509032201612827f },
    { 0.92387953251128674f, -0.38268343236508977f },
    { 0.83146961230254524f, -0.55557023301960218f },
    { 0.70710678118654752f, -0.70710678118654752f },
    { 0.55557023301960222f, -0.83146961230254524f },
    { 0.38268343236508977f, -0.92387953251128674f },
    { 0.19509032201612827f, -0.98078528040323044f },
    { 0.0f,                 -1.0f                 },
    {-0.19509032201612827f, -0.98078528040323044f },
    {-0.38268343236508977f, -0.92387953251128674f },
    {-0.55557023301960218f, -0.83146961230254524f },
    {-0.70710678118654752f, -0.70710678118654752f },
    {-0.83146961230254524f, -0.55557023301960222f },
    {-0.92387953251128674f, -0.38268343236508977f },
    {-0.98078528040323044f, -0.19509032201612827f }
};

#define C_S2 0.70710678118654752440f
#define C16A 0.92387953251128676f
#define C16B 0.38268343236508977f

// ---------------- small DFTs in registers ----------------
#define DFT4F(a,b,c,d,o0,o1,o2,o3) do { \
    float2 _t0 = cadd(a,c), _t1 = csub(a,c); \
    float2 _t2 = cadd(b,d), _t3 = mul_negi(csub(b,d)); \
    o0 = cadd(_t0,_t2); o1 = cadd(_t1,_t3); \
    o2 = csub(_t0,_t2); o3 = csub(_t1,_t3); } while(0)
#define DFT4I(a,b,c,d,o0,o1,o2,o3) do { \
    float2 _t0 = cadd(a,c), _t1 = csub(a,c); \
    float2 _t2 = cadd(b,d), _t3 = mul_posi(csub(b,d)); \
    o0 = cadd(_t0,_t2); o1 = cadd(_t1,_t3); \
    o2 = csub(_t0,_t2); o3 = csub(_t1,_t3); } while(0)

__device__ __forceinline__ void dft16(float2 x[16]) {
    float2 A0[4], A1[4], A2[4], A3[4];
    DFT4F(x[0], x[4], x[8],  x[12], A0[0], A0[1], A0[2], A0[3]);
    DFT4F(x[1], x[5], x[9],  x[13], A1[0], A1[1], A1[2], A1[3]);
    DFT4F(x[2], x[6], x[10], x[14], A2[0], A2[1], A2[2], A2[3]);
    DFT4F(x[3], x[7], x[11], x[15], A3[0], A3[1], A3[2], A3[3]);
    A1[1] = cmul(A1[1], make_float2( C16A, -C16B));
    A1[2] = cmul(A1[2], make_float2( C_S2, -C_S2));
    A1[3] = cmul(A1[3], make_float2( C16B, -C16A));
    A2[1] = cmul(A2[1], make_float2( C_S2, -C_S2));
    A2[2] = mul_negi(A2[2]);
    A2[3] = cmul(A2[3], make_float2(-C_S2, -C_S2));
    A3[1] = cmul(A3[1], make_float2( C16B, -C16A));
    A3[2] = cmul(A3[2], make_float2(-C_S2, -C_S2));
    A3[3] = cmul(A3[3], make_float2(-C16A,  C16B));
#pragma unroll
    for (int m = 0; m < 4; m++)
        DFT4F(A0[m], A1[m], A2[m], A3[m], x[m], x[m+4], x[m+8], x[m+12]);
}

__device__ __forceinline__ void idft16(float2 x[16]) {
    float2 A0[4], A1[4], A2[4], A3[4];
    DFT4I(x[0], x[4], x[8],  x[12], A0[0], A0[1], A0[2], A0[3]);
    DFT4I(x[1], x[5], x[9],  x[13], A1[0], A1[1], A1[2], A1[3]);
    DFT4I(x[2], x[6], x[10], x[14], A2[0], A2[1], A2[2], A2[3]);
    DFT4I(x[3], x[7], x[11], x[15], A3[0], A3[1], A3[2], A3[3]);
    A1[1] = cmul(A1[1], make_float2( C16A,  C16B));
    A1[2] = cmul(A1[2], make_float2( C_S2,  C_S2));
    A1[3] = cmul(A1[3], make_float2( C16B,  C16A));
    A2[1] = cmul(A2[1], make_float2( C_S2,  C_S2));
    A2[2] = mul_posi(A2[2]);
    A2[3] = cmul(A2[3], make_float2(-C_S2,  C_S2));
    A3[1] = cmul(A3[1], make_float2( C16B,  C16A));
    A3[2] = cmul(A3[2], make_float2(-C_S2,  C_S2));
    A3[3] = cmul(A3[3], make_float2(-C16A, -C16B));
#pragma unroll
    for (int m = 0; m < 4; m++)
        DFT4I(A0[m], A1[m], A2[m], A3[m], x[m], x[m+4], x[m+8], x[m+12]);
}

__device__ __forceinline__ void dft5f(float2 a0, float2 a1, float2 a2,
                                      float2 a3, float2 a4, float2 o[5]) {
#pragma unroll
    for (int p = 0; p < 5; p++) {
        float2 acc = a0;
        acc = cadd(acc, cmul(a1, W5c[p % 5]));
        acc = cadd(acc, cmul(a2, W5c[(2*p) % 5]));
        acc = cadd(acc, cmul(a3, W5c[(3*p) % 5]));
        acc = cadd(acc, cmul(a4, W5c[(4*p) % 5]));
        o[p] = acc;
    }
}
__device__ __forceinline__ void dft5i(float2 a0, float2 a1, float2 a2,
                                      float2 a3, float2 a4, float2 o[5]) {
#pragma unroll
    for (int p = 0; p < 5; p++) {
        float2 acc = a0;
        acc = cadd(acc, cmulc(a1, W5c[p % 5]));
        acc = cadd(acc, cmulc(a2, W5c[(2*p) % 5]));
        acc = cadd(acc, cmulc(a3, W5c[(3*p) % 5]));
        acc = cadd(acc, cmulc(a4, W5c[(4*p) % 5]));
        o[p] = acc;
    }
}

__device__ __forceinline__ void dft10(float2 x[10]) {
    float2 B0[5], B1[5];
    dft5f(x[0], x[2], x[4], x[6], x[8], B0);
    dft5f(x[1], x[3], x[5], x[7], x[9], B1);
#pragma unroll
    for (int m = 0; m < 5; m++) {
        float2 t = cmul(B1[m], W10c[m]);
        x[m]     = cadd(B0[m], t);
        x[m + 5] = csub(B0[m], t);
    }
}
__device__ __forceinline__ void idft10(float2 x[10]) {
    float2 B0[5], B1[5];
    dft5i(x[0], x[2], x[4], x[6], x[8], B0);
    dft5i(x[1], x[3], x[5], x[7], x[9], B1);
#pragma unroll
    for (int m = 0; m < 5; m++) {
        float2 t = cmulc(B1[m], W10c[m]);
        x[m]     = cadd(B0[m], t);
        x[m + 5] = csub(B0[m], t);
    }
}

// 20 = 2 x 10 (DIT)
__device__ __forceinline__ void dft20f(float2 x[20]) {
    float2 E[10], O[10];
#pragma unroll
    for (int q = 0; q < 10; q++) { E[q] = x[2*q]; O[q] = x[2*q+1]; }
    dft10(E); dft10(O);
#pragma unroll
    for (int m = 0; m < 10; m++) {
        float2 t = cmul(O[m], W20c[m]);
        x[m]      = cadd(E[m], t);
        x[m + 10] = csub(E[m], t);
    }
}
__device__ __forceinline__ void dft20i(float2 y[20]) {
    float2 A[10], B[10];
#pragma unroll
    for (int m = 0; m < 10; m++) {
        A[m] = cadd(y[m], y[m+10]);
        B[m] = cmulc(csub(y[m], y[m+10]), W20c[m]);
    }
    idft10(A); idft10(B);
#pragma unroll
    for (int q = 0; q < 10; q++) { y[2*q] = A[q]; y[2*q+1] = B[q]; }
}

// 25 = 5 x 5 Cooley-Tukey
__device__ __forceinline__ void dft25f(float2 x[25]) {
    float2 B[5][5];
#pragma unroll
    for (int bb = 0; bb < 5; bb++)
        dft5f(x[bb], x[5+bb], x[10+bb], x[15+bb], x[20+bb], B[bb]);
#pragma unroll
    for (int bb = 1; bb < 5; bb++)
#pragma unroll
        for (int c = 1; c < 5; c++)
            B[bb][c] = cmul(B[bb][c], W25c[bb*c]);
#pragma unroll
    for (int c = 0; c < 5; c++) {
        float2 o[5];
        dft5f(B[0][c], B[1][c], B[2][c], B[3][c], B[4][c], o);
#pragma unroll
        for (int d = 0; d < 5; d++) x[c + 5*d] = o[d];
    }
}
__device__ __forceinline__ void dft25i(float2 x[25]) {
    float2 D[5][5];   // D[c][b]
#pragma unroll
    for (int c = 0; c < 5; c++)
        dft5i(x[c], x[c+5], x[c+10], x[c+15], x[c+20], D[c]);
#pragma unroll
    for (int c = 1; c < 5; c++)
#pragma unroll
        for (int bb = 1; bb < 5; bb++)
            D[c][bb] = cmulc(D[c][bb], W25c[bb*c]);
#pragma unroll
    for (int bb = 0; bb < 5; bb++) {
        float2 o[5];
        dft5i(D[0][bb], D[1][bb], D[2][bb], D[3][bb], D[4][bb], o);
#pragma unroll
        for (int a = 0; a < 5; a++) x[5*a + bb] = o[a];
    }
}

// ---------------- FFT stages (plan: 32, 20, 25) ----------------
__device__ __forceinline__ void stage32_fwd(float2* sm) {
    const int h = 500;   // NS = 16000, stride = 1
    for (int t = threadIdx.x; t < h; t += NTH) {
        float2* b = sm + t;
        float2 e[16], o[16];
#pragma unroll
        for (int q = 0; q < 16; q++) { e[q] = b[(2*q)*h]; o[q] = b[(2*q+1)*h]; }
        dft16(e); dft16(o);
        float2 T  = g_tw[t];
        float2 T2 = cmul(T, T), T4 = cmul(T2, T2);
        float2 T8 = cmul(T4, T4), T16 = cmul(T8, T8);
        float2 cur = make_float2(1.f, 0.f);
#pragma unroll
        for (int m = 0; m < 16; m++) {
            float2 w  = cmul(o[m], W32c[m]);
            float2 lo = cadd(e[m], w), hi = csub(e[m], w);
            if (m == 0) { b[0] = lo; b[16*h] = cmul(hi, T16); }
            else {
                b[m*h]      = cmul(lo, cur);
                b[(m+16)*h] = cmul(cmul(hi, cur), T16);
            }
            cur = cmul(cur, T);
        }
    }
    __syncthreads();
}

__device__ __forceinline__ void stage32_inv(float2* sm) {
    const int h = 500;
    for (int t = threadIdx.x; t < h; t += NTH) {
        float2* b = sm + t;
        float2 T  = g_tw[t];
        float2 T2 = cmul(T, T), T4 = cmul(T2, T2);
        float2 T8 = cmul(T4, T4), T16 = cmul(T8, T8);
        float2 y[32];
        y[0]  = b[0];
        y[16] = cmulc(b[16*h], T16);
        float2 cur = make_float2(1.f, 0.f);
#pragma unroll
        for (int m = 1; m < 16; m++) {
            cur = cmul(cur, T);                 // cur = T^m
            y[m]    = cmulc(b[m*h], cur);
            y[m+16] = cmulc(b[(m+16)*h], cmul(cur, T16));
        }
#pragma unroll
        for (int m = 0; m < 16; m++) {
            float2 a = cadd(y[m], y[m+16]);
            float2 d = cmulc(csub(y[m], y[m+16]), W32c[m]);
            y[m] = a; y[m+16] = d;
        }
        idft16(y); idft16(y + 16);
#pragma unroll
        for (int q = 0; q < 16; q++) { b[(2*q)*h] = y[q]; b[(2*q+1)*h] = y[q+16]; }
    }
    __syncthreads();
}

__device__ __forceinline__ void stage20_fwd(float2* sm) {
    // NS = 500, h = 25, stride = 32
    for (int u = threadIdx.x; u < 800; u += NTH) {
        int blk = u / 25, t = u - blk * 25;
        float2* b = sm + blk * 500 + t;
        float2 x[20];
#pragma unroll
        for (int q = 0; q < 20; q++) x[q] = b[q*25];
        dft20f(x);
        float2 T = g_tw[t * 32];
        float2 cur = T;
#pragma unroll
        for (int p = 1; p < 20; p++) { x[p] = cmul(x[p], cur); cur = cmul(cur, T); }
#pragma unroll
        for (int p = 0; p < 20; p++) b[p*25] = x[p];
    }
    __syncthreads();
}

__device__ __forceinline__ void stage20_inv(float2* sm) {
    for (int u = threadIdx.x; u < 800; u += NTH) {
        int blk = u / 25, t = u - blk * 25;
        float2* b = sm + blk * 500 + t;
        float2 T = g_tw[t * 32];
        float2 y[20];
        y[0] = b[0];
        float2 cur = T;
#pragma unroll
        for (int p = 1; p < 20; p++) { y[p] = cmulc(b[p*25], cur); cur = cmul(cur, T); }
        dft20i(y);
#pragma unroll
        for (int p = 0; p < 20; p++) b[p*25] = y[p];
    }
    __syncthreads();
}

__device__ __forceinline__ void stage25_fwd(float2* sm) {
    // NS = 25, h = 1, t = 0 -> no twiddles
    for (int u = threadIdx.x; u < 640; u += NTH) {
        float2* b = sm + u * 25;
        float2 x[25];
#pragma unroll
        for (int q = 0; q < 25; q++) x[q] = b[q];
        dft25f(x);
#pragma unroll
        for (int p = 0; p < 25; p++) b[p] = x[p];
    }
    __syncthreads();
}

__device__ __forceinline__ void stage25_inv(float2* sm) {
    for (int u = threadIdx.x; u < 640; u += NTH) {
        float2* b = sm + u * 25;
        float2 x[25];
#pragma unroll
        for (int q = 0; q < 25; q++) x[q] = b[q];
        dft25i(x);
#pragma unroll
        for (int p = 0; p < 25; p++) b[p] = x[p];
    }
    __syncthreads();
}

__device__ __forceinline__ void fft_fwd(float2* sm) {
    stage32_fwd(sm);
    stage20_fwd(sm);
    stage25_fwd(sm);
}
__device__ __forceinline__ void fft_inv(float2* sm) {
    stage25_inv(sm);
    stage20_inv(sm);
    stage32_inv(sm);
}

// ---------------- setup: twiddles + digit-reversal + norm clear -------------
__global__ void k_setup() {
    int j = blockIdx.x * blockDim.x + threadIdx.x;
    if (j >= N_FFT) return;
    double a = -2.0 * 3.14159265358979323846 * (double)j / (double)N_FFT;
    double sn, cs;
    sincos(a, &sn, &cs);
    g_tw[j] = make_float2((float)cs, (float)sn);
    g_norm[j] = 0.f;

    // sigma for stage plan {32, 20, 25}
    const int RADS[3] = {32, 20, 25};
    int p[3];
    int jj = j, len = N_FFT;
    for (int s = 0; s < 3; s++) {
        int h = len / RADS[s];
        p[s] = jj / h;
        jj -= p[s] * h;
        len = h;
    }
    int f = 0;
    for (int s = 2; s >= 0; s--) f = p[s] + RADS[s] * f;
    g_sig[j] = f;
    g_isig[f] = j;
}

// One block per sketch row: find the single +-1 nonzero; early-exit per chunk.
__global__ void k_extract(const float* __restrict__ sk1,
                          const float* __restrict__ sk2) {
    int r = blockIdx.x;
    const float* row = (r < IN_DIM) ? (sk1 + (size_t)r * N_FFT)
                                    : (sk2 + (size_t)(r - IN_DIM) * N_FFT);
    const float4* row4 = (const float4*)row;
    __shared__ int found;
    if (threadIdx.x == 0) found = 0;
    __syncthreads();
    for (int base = 0; base < N_FFT / 4; base += blockDim.x) {
        int j = base + threadIdx.x;
        if (j < N_FFT / 4) {
            float4 v = row4[j];
            if (v.x != 0.f || v.y != 0.f || v.z != 0.f || v.w != 0.f) {
                int   c   = (v.x != 0.f) ? 0 : (v.y != 0.f) ? 1 : (v.z != 0.f) ? 2 : 3;
                float val = (c == 0) ? v.x : (c == 1) ? v.y : (c == 2) ? v.z : v.w;
                g_h[r] = 4 * j + c;
                g_s[r] = val;
                found = 1;
            }
        }
        __syncthreads();
        if (found) break;
    }
}

// ---------------- fused main kernel ----------------
__global__ void __launch_bounds__(NTH, 1)
k_main(const float* __restrict__ x1, const float* __restrict__ x2,
       float* __restrict__ out) {
    extern __shared__ float2 sm[];
    int b = blockIdx.x;

    float4* sm4 = (float4*)sm;
    for (int i = threadIdx.x; i < N_FFT / 2; i += NTH)
        sm4[i] = make_float4(0.f, 0.f, 0.f, 0.f);
    __syncthreads();

    // count-sketch scatter: p1 -> real, p2 -> imag
    const float* r1 = x1 + (size_t)b * IN_DIM;
    const float* r2 = x2 + (size_t)b * IN_DIM;
    for (int k = threadIdx.x; k < IN_DIM; k += NTH) {
        atomicAdd(&sm[g_h[k]].x,          g_s[k]          * r1[k]);
        atomicAdd(&sm[g_h[IN_DIM + k]].y, g_s[IN_DIM + k] * r2[k]);
    }
    __syncthreads();

    fft_fwd(sm);

    // Hermitian separation + pointwise product in scrambled order.
    for (int j = threadIdx.x; j < N_FFT; j += NTH) {
        int k = g_sig[j];
        if (k > N_FFT / 2) continue;
        if (k == 0 || k == N_FFT / 2) {
            float2 Z = sm[j];
            sm[j] = make_float2(Z.x * Z.y, 0.f);
        } else {
            int jm = g_isig[N_FFT - k];
            float2 Zk = sm[j], Zm = sm[jm];
            float2 F1 = make_float2(0.5f * (Zk.x + Zm.x), 0.5f * (Zk.y - Zm.y));
            float2 F2 = make_float2(0.5f * (Zk.y + Zm.y), -0.5f * (Zk.x - Zm.x));
            float2 G = cmul(F1, F2);
            sm[j]  = G;
            sm[jm] = make_float2(G.x, -G.y);
        }
    }
    __syncthreads();

    fft_inv(sm);   // natural order, unnormalized inverse (x N built in)

    // vectorized signed-sqrt store + fused column-norm accumulation
    // (ss^2 == |c| exactly, so accumulate |c|)
    float4* dst4 = (float4*)(out + (size_t)b * N_FFT);
    for (int j4 = threadIdx.x; j4 < N_FFT / 4; j4 += NTH) {
        float c0 = sm[4*j4 + 0].x, c1 = sm[4*j4 + 1].x;
        float c2 = sm[4*j4 + 2].x, c3 = sm[4*j4 + 3].x;
        float4 v;
        v.x = copysignf(sqrtf(fabsf(c0)), c0);
        v.y = copysignf(sqrtf(fabsf(c1)), c1);
        v.z = copysignf(sqrtf(fabsf(c2)), c2);
        v.w = copysignf(sqrtf(fabsf(c3)), c3);
        dst4[j4] = v;
        atomicAdd(&g_norm[4*j4 + 0], fabsf(c0));
        atomicAdd(&g_norm[4*j4 + 1], fabsf(c1));
        atomicAdd(&g_norm[4*j4 + 2], fabsf(c2));
        atomicAdd(&g_norm[4*j4 + 3], fabsf(c3));
    }
}

__global__ void k_normalize(float* __restrict__ out) {
    int i = blockIdx.x * blockDim.x + threadIdx.x;
    if (i >= BATCH * (N_FFT / 4)) return;
    int c4 = i % (N_FFT / 4);
    float4 nv = ((const float4*)g_norm)[c4];
    float4* o4 = (float4*)out;
    float4 v = o4[i];
    v.x /= fmaxf(sqrtf(nv.x), 1e-12f);
    v.y /= fmaxf(sqrtf(nv.y), 1e-12f);
    v.z /= fmaxf(sqrtf(nv.z), 1e-12f);
    v.w /= fmaxf(sqrtf(nv.w), 1e-12f);
    o4[i] = v;
}

// ---------------- launch ----------------
extern "C" void kernel_launch(void* const* d_in, const int* in_sizes, int n_in,
                              void* d_out, int out_size) {
    const float* x1  = (const float*)d_in[0];
    const float* x2  = (const float*)d_in[1];
    const float* sk1 = (const float*)d_in[2];
    const float* sk2 = (const float*)d_in[3];
    float* out = (float*)d_out;

    const int smem = N_FFT * sizeof(float2);  // 128000 B
    cudaFuncSetAttribute(k_main, cudaFuncAttributeMaxDynamicSharedMemorySize, smem);

    k_setup<<<(N_FFT + 255) / 256, 256>>>();
    k_extract<<<2 * IN_DIM, 256>>>(sk1, sk2);
    k_main<<<BATCH, NTH, smem>>>(x1, x2, out);
    k_normalize<<<(BATCH * N_FFT / 4 + 255) / 256, 256>>>(out);
}

// round 7
// speedup vs baseline: 1.0858x; 1.0858x over previous
#include <cuda_runtime.h>
#include <cuda_bf16.h>
#include <math.h>

#define N_FFT 16000
#define BATCH 512
#define IN_DIM 2048
#define NTH 1024

// ---------------- scratch (static __device__, no allocation) ----------------
__device__ int    g_h[2 * IN_DIM];
__device__ float  g_s[2 * IN_DIM];
__device__ float2 g_tw[N_FFT];      // W_N^j = exp(-2*pi*i*j/N)
__device__ int    g_sig[N_FFT];     // scrambled position -> natural frequency
__device__ int    g_isig[N_FFT];    // natural frequency -> scrambled position
__device__ __align__(16) float g_norm[N_FFT];  // sum |c| -> reciprocal norm

// ---------------- complex helpers ----------------
__device__ __forceinline__ float2 cmul(float2 a, float2 b) {
    return make_float2(a.x * b.x - a.y * b.y, a.x * b.y + a.y * b.x);
}
__device__ __forceinline__ float2 cmulc(float2 a, float2 b) {  // a * conj(b)
    return make_float2(a.x * b.x + a.y * b.y, a.y * b.x - a.x * b.y);
}
__device__ __forceinline__ float2 cadd(float2 a, float2 b) {
    return make_float2(a.x + b.x, a.y + b.y);
}
__device__ __forceinline__ float2 csub(float2 a, float2 b) {
    return make_float2(a.x - b.x, a.y - b.y);
}
__device__ __forceinline__ float2 mul_negi(float2 a) { return make_float2(a.y, -a.x); }
__device__ __forceinline__ float2 mul_posi(float2 a) { return make_float2(-a.y, a.x); }

// W5^j
__constant__ float2 W5c[5] = {
    { 1.0f,                  0.0f                 },
    { 0.30901699437494742f, -0.95105651629515357f },
    {-0.80901699437494742f, -0.58778525229247314f },
    {-0.80901699437494745f,  0.58778525229247312f },
    { 0.30901699437494740f,  0.95105651629515364f }
};
// W10^m, m=0..4
__constant__ float2 W10c[5] = {
    { 1.0f,                  0.0f                 },
    { 0.80901699437494742f, -0.58778525229247312f },
    { 0.30901699437494742f, -0.95105651629515357f },
    {-0.30901699437494742f, -0.95105651629515357f },
    {-0.80901699437494742f, -0.58778525229247312f }
};

#define C_S2 0.70710678118654752440f
#define C16A 0.92387953251128676f
#define C16B 0.38268343236508977f

// ---------------- small DFTs in registers ----------------
#define DFT4F(a,b,c,d,o0,o1,o2,o3) do { \
    float2 _t0 = cadd(a,c), _t1 = csub(a,c); \
    float2 _t2 = cadd(b,d), _t3 = mul_negi(csub(b,d)); \
    o0 = cadd(_t0,_t2); o1 = cadd(_t1,_t3); \
    o2 = csub(_t0,_t2); o3 = csub(_t1,_t3); } while(0)
#define DFT4I(a,b,c,d,o0,o1,o2,o3) do { \
    float2 _t0 = cadd(a,c), _t1 = csub(a,c); \
    float2 _t2 = cadd(b,d), _t3 = mul_posi(csub(b,d)); \
    o0 = cadd(_t0,_t2); o1 = cadd(_t1,_t3); \
    o2 = csub(_t0,_t2); o3 = csub(_t1,_t3); } while(0)

__device__ __forceinline__ void dft16(float2 x[16]) {
    float2 A0[4], A1[4], A2[4], A3[4];
    DFT4F(x[0], x[4], x[8],  x[12], A0[0], A0[1], A0[2], A0[3]);
    DFT4F(x[1], x[5], x[9],  x[13], A1[0], A1[1], A1[2], A1[3]);
    DFT4F(x[2], x[6], x[10], x[14], A2[0], A2[1], A2[2], A2[3]);
    DFT4F(x[3], x[7], x[11], x[15], A3[0], A3[1], A3[2], A3[3]);
    A1[1] = cmul(A1[1], make_float2( C16A, -C16B));
    A1[2] = cmul(A1[2], make_float2( C_S2, -C_S2));
    A1[3] = cmul(A1[3], make_float2( C16B, -C16A));
    A2[1] = cmul(A2[1], make_float2( C_S2, -C_S2));
    A2[2] = mul_negi(A2[2]);
    A2[3] = cmul(A2[3], make_float2(-C_S2, -C_S2));
    A3[1] = cmul(A3[1], make_float2( C16B, -C16A));
    A3[2] = cmul(A3[2], make_float2(-C_S2, -C_S2));
    A3[3] = cmul(A3[3], make_float2(-C16A,  C16B));
#pragma unroll
    for (int m = 0; m < 4; m++)
        DFT4F(A0[m], A1[m], A2[m], A3[m], x[m], x[m+4], x[m+8], x[m+12]);
}

__device__ __forceinline__ void idft16(float2 x[16]) {
    float2 A0[4], A1[4], A2[4], A3[4];
    DFT4I(x[0], x[4], x[8],  x[12], A0[0], A0[1], A0[2], A0[3]);
    DFT4I(x[1], x[5], x[9],  x[13], A1[0], A1[1], A1[2], A1[3]);
    DFT4I(x[2], x[6], x[10], x[14], A2[0], A2[1], A2[2], A2[3]);
    DFT4I(x[3], x[7], x[11], x[15], A3[0], A3[1], A3[2], A3[3]);
    A1[1] = cmul(A1[1], make_float2( C16A,  C16B));
    A1[2] = cmul(A1[2], make_float2( C_S2,  C_S2));
    A1[3] = cmul(A1[3], make_float2( C16B,  C16A));
    A2[1] = cmul(A2[1], make_float2( C_S2,  C_S2));
    A2[2] = mul_posi(A2[2]);
    A2[3] = cmul(A2[3], make_float2(-C_S2,  C_S2));
    A3[1] = cmul(A3[1], make_float2( C16B,  C16A));
    A3[2] = cmul(A3[2], make_float2(-C_S2,  C_S2));
    A3[3] = cmul(A3[3], make_float2(-C16A, -C16B));
#pragma unroll
    for (int m = 0; m < 4; m++)
        DFT4I(A0[m], A1[m], A2[m], A3[m], x[m], x[m+4], x[m+8], x[m+12]);
}

__device__ __forceinline__ void dft5f(float2 a0, float2 a1, float2 a2,
                                      float2 a3, float2 a4, float2 o[5]) {
#pragma unroll
    for (int p = 0; p < 5; p++) {
        float2 acc = a0;
        acc = cadd(acc, cmul(a1, W5c[p % 5]));
        acc = cadd(acc, cmul(a2, W5c[(2*p) % 5]));
        acc = cadd(acc, cmul(a3, W5c[(3*p) % 5]));
        acc = cadd(acc, cmul(a4, W5c[(4*p) % 5]));
        o[p] = acc;
    }
}
__device__ __forceinline__ void dft5i(float2 a0, float2 a1, float2 a2,
                                      float2 a3, float2 a4, float2 o[5]) {
#pragma unroll
    for (int p = 0; p < 5; p++) {
        float2 acc = a0;
        acc = cadd(acc, cmulc(a1, W5c[p % 5]));
        acc = cadd(acc, cmulc(a2, W5c[(2*p) % 5]));
        acc = cadd(acc, cmulc(a3, W5c[(3*p) % 5]));
        acc = cadd(acc, cmulc(a4, W5c[(4*p) % 5]));
        o[p] = acc;
    }
}

__device__ __forceinline__ void dft10(float2 x[10]) {
    float2 B0[5], B1[5];
    dft5f(x[0], x[2], x[4], x[6], x[8], B0);
    dft5f(x[1], x[3], x[5], x[7], x[9], B1);
#pragma unroll
    for (int m = 0; m < 5; m++) {
        float2 t = cmul(B1[m], W10c[m]);
        x[m]     = cadd(B0[m], t);
        x[m + 5] = csub(B0[m], t);
    }
}
__device__ __forceinline__ void idft10(float2 x[10]) {
    float2 B0[5], B1[5];
    dft5i(x[0], x[2], x[4], x[6], x[8], B0);
    dft5i(x[1], x[3], x[5], x[7], x[9], B1);
#pragma unroll
    for (int m = 0; m < 5; m++) {
        float2 t = cmulc(B1[m], W10c[m]);
        x[m]     = cadd(B0[m], t);
        x[m + 5] = csub(B0[m], t);
    }
}

// ---------------- FFT stages (plan: 16, 10, 10, 10) ----------------
// Serial twiddle chains keep live registers low (NTH=1024 -> 64-reg cap).

__device__ __forceinline__ void stage16_fwd(float2* sm) {
    const int h = 1000;                       // NS = 16000, stride = 1
    for (int t = threadIdx.x; t < h; t += NTH) {
        float2* b = sm + t;
        float2 x[16];
#pragma unroll
        for (int q = 0; q < 16; q++) x[q] = b[q * h];
        dft16(x);
        float2 T = g_tw[t];
        b[0] = x[0];
        float2 cur = T;
#pragma unroll
        for (int p = 1; p < 16; p++) {
            b[p * h] = cmul(x[p], cur);
            cur = cmul(cur, T);
        }
    }
    __syncthreads();
}

template<int NS, int STRIDE>
__device__ __forceinline__ void stage10_fwd(float2* sm) {
    const int h = NS / 10;
    for (int u = threadIdx.x; u < N_FFT / 10; u += NTH) {
        int blk = u / h, t = u - blk * h;
        float2* b = sm + blk * NS + t;
        float2 x[10];
#pragma unroll
        for (int q = 0; q < 10; q++) x[q] = b[q * h];
        dft10(x);
        if (NS != 10) {                       // last stage: t==0, no twiddles
            float2 T = g_tw[t * STRIDE];
            float2 cur = T;
#pragma unroll
            for (int p = 1; p < 10; p++) {
                x[p] = cmul(x[p], cur);
                cur = cmul(cur, T);
            }
        }
#pragma unroll
        for (int p = 0; p < 10; p++) b[p * h] = x[p];
    }
    __syncthreads();
}

template<int NS, int STRIDE>
__device__ __forceinline__ void stage10_inv(float2* sm) {
    const int h = NS / 10;
    for (int u = threadIdx.x; u < N_FFT / 10; u += NTH) {
        int blk = u / h, t = u - blk * h;
        float2* b = sm + blk * NS + t;
        float2 y[10];
        y[0] = b[0];
        if (NS != 10) {
            float2 T = g_tw[t * STRIDE];
            float2 cur = T;
#pragma unroll
            for (int p = 1; p < 10; p++) {
                y[p] = cmulc(b[p * h], cur);
                cur = cmul(cur, T);
            }
        } else {
#pragma unroll
            for (int p = 1; p < 10; p++) y[p] = b[p * h];
        }
        idft10(y);
#pragma unroll
        for (int q = 0; q < 10; q++) b[q * h] = y[q];
    }
    __syncthreads();
}

// Final inverse stage fused with signed-sqrt output + column-norm accumulation.
// Natural-order result for index q*1000+t lands in y[q]; write straight to
// gmem (coalesced: consecutive t across lanes) and REDG |c| into g_norm.
__device__ __forceinline__ void stage16_inv_store(float2* sm, float* dst) {
    const int h = 1000;
    for (int t = threadIdx.x; t < h; t += NTH) {
        float2* b = sm + t;
        float2 T = g_tw[t];
        float2 y[16];
        y[0] = b[0];
        float2 cur = T;
#pragma unroll
        for (int p = 1; p < 16; p++) {
            y[p] = cmulc(b[p * h], cur);
            cur = cmul(cur, T);
        }
        idft16(y);
#pragma unroll
        for (int q = 0; q < 16; q++) {
            float c = y[q].x;
            float a = fabsf(c);
            dst[q * 1000 + t] = copysignf(sqrtf(a), c);
            atomicAdd(&g_norm[q * 1000 + t], a);   // ss^2 == |c| exactly
        }
    }
}

__device__ __forceinline__ void fft_fwd(float2* sm) {
    stage16_fwd(sm);                    // 16000 -> 1000
    stage10_fwd<1000, 16>(sm);          // 1000  -> 100
    stage10_fwd<100, 160>(sm);          // 100   -> 10
    stage10_fwd<10, 1600>(sm);          // 10    -> 1 (no twiddles)
}

// ---------------- setup: twiddles + digit-reversal + norm clear -------------
__global__ void k_setup() {
    int j = blockIdx.x * blockDim.x + threadIdx.x;
    if (j >= N_FFT) return;
    double a = -2.0 * 3.14159265358979323846 * (double)j / (double)N_FFT;
    double sn, cs;
    sincos(a, &sn, &cs);
    g_tw[j] = make_float2((float)cs, (float)sn);
    g_norm[j] = 0.f;

    // sigma for stage plan {16,10,10,10}
    const int RADS[4] = {16, 10, 10, 10};
    int p[4];
    int jj = j, len = N_FFT;
    for (int s = 0; s < 4; s++) {
        int h = len / RADS[s];
        p[s] = jj / h;
        jj -= p[s] * h;
        len = h;
    }
    int f = 0;
    for (int s = 3; s >= 0; s--) f = p[s] + RADS[s] * f;
    g_sig[j] = f;
    g_isig[f] = j;
}

// One block per sketch row: find the single +-1 nonzero; early-exit per chunk.
__global__ void k_extract(const float* __restrict__ sk1,
                          const float* __restrict__ sk2) {
    int r = blockIdx.x;
    const float* row = (r < IN_DIM) ? (sk1 + (size_t)r * N_FFT)
                                    : (sk2 + (size_t)(r - IN_DIM) * N_FFT);
    const float4* row4 = (const float4*)row;
    __shared__ int found;
    if (threadIdx.x == 0) found = 0;
    __syncthreads();
    for (int base = 0; base < N_FFT / 4; base += blockDim.x) {
        int j = base + threadIdx.x;
        if (j < N_FFT / 4) {
            float4 v = row4[j];
            if (v.x != 0.f || v.y != 0.f || v.z != 0.f || v.w != 0.f) {
                int   c   = (v.x != 0.f) ? 0 : (v.y != 0.f) ? 1 : (v.z != 0.f) ? 2 : 3;
                float val = (c == 0) ? v.x : (c == 1) ? v.y : (c == 2) ? v.z : v.w;
                g_h[r] = 4 * j + c;
                g_s[r] = val;
                found = 1;
            }
        }
        __syncthreads();
        if (found) break;
    }
}

// ---------------- fused main kernel ----------------
__global__ void __launch_bounds__(NTH, 1)
k_main(const float* __restrict__ x1, const float* __restrict__ x2,
       float* __restrict__ out) {
    extern __shared__ float2 sm[];
    int b = blockIdx.x;

    float4* sm4 = (float4*)sm;
    for (int i = threadIdx.x; i < N_FFT / 2; i += NTH)
        sm4[i] = make_float4(0.f, 0.f, 0.f, 0.f);
    __syncthreads();

    // count-sketch scatter: p1 -> real, p2 -> imag
    const float* r1 = x1 + (size_t)b * IN_DIM;
    const float* r2 = x2 + (size_t)b * IN_DIM;
    for (int k = threadIdx.x; k < IN_DIM; k += NTH) {
        atomicAdd(&sm[g_h[k]].x,          g_s[k]          * r1[k]);
        atomicAdd(&sm[g_h[IN_DIM + k]].y, g_s[IN_DIM + k] * r2[k]);
    }
    __syncthreads();

    fft_fwd(sm);

    // Hermitian separation + pointwise product in scrambled order.
    for (int j = threadIdx.x; j < N_FFT; j += NTH) {
        int k = g_sig[j];
        if (k > N_FFT / 2) continue;
        if (k == 0 || k == N_FFT / 2) {
            float2 Z = sm[j];
            sm[j] = make_float2(Z.x * Z.y, 0.f);
        } else {
            int jm = g_isig[N_FFT - k];
            float2 Zk = sm[j], Zm = sm[jm];
            float2 F1 = make_float2(0.5f * (Zk.x + Zm.x), 0.5f * (Zk.y - Zm.y));
            float2 F2 = make_float2(0.5f * (Zk.y + Zm.y), -0.5f * (Zk.x - Zm.x));
            float2 G = cmul(F1, F2);
            sm[j]  = G;
            sm[jm] = make_float2(G.x, -G.y);
        }
    }
    __syncthreads();

    // inverse: 3 smem stages + final stage fused with store
    stage10_inv<10, 1600>(sm);
    stage10_inv<100, 160>(sm);
    stage10_inv<1000, 16>(sm);
    stage16_inv_store(sm, out + (size_t)b * N_FFT);
}

// turn accumulated sums into reciprocal norms (in place)
__global__ void k_rnorm() {
    int d = blockIdx.x * blockDim.x + threadIdx.x;
    if (d < N_FFT)
        g_norm[d] = 1.0f / fmaxf(sqrtf(g_norm[d]), 1e-12f);
}

__global__ void k_normalize(float* __restrict__ out) {
    int i = blockIdx.x * blockDim.x + threadIdx.x;
    if (i >= BATCH * (N_FFT / 4)) return;
    int c4 = i % (N_FFT / 4);
    float4 nv = ((const float4*)g_norm)[c4];
    float4* o4 = (float4*)out;
    float4 v = o4[i];
    v.x *= nv.x; v.y *= nv.y; v.z *= nv.z; v.w *= nv.w;
    o4[i] = v;
}

// ---------------- launch ----------------
extern "C" void kernel_launch(void* const* d_in, const int* in_sizes, int n_in,
                              void* d_out, int out_size) {
    const float* x1  = (const float*)d_in[0];
    const float* x2  = (const float*)d_in[1];
    const float* sk1 = (const float*)d_in[2];
    const float* sk2 = (const float*)d_in[3];
    float* out = (float*)d_out;

    const int smem = N_FFT * sizeof(float2);  // 128000 B
    cudaFuncSetAttribute(k_main, cudaFuncAttributeMaxDynamicSharedMemorySize, smem);

    k_setup<<<(N_FFT + 255) / 256, 256>>>();
    k_extract<<<2 * IN_DIM, 256>>>(sk1, sk2);
    k_main<<<BATCH, NTH, smem>>>(x1, x2, out);
    k_rnorm<<<(N_FFT + 255) / 256, 256>>>();
    k_normalize<<<(BATCH * N_FFT / 4 + 255) / 256, 256>>>(out);
}

// round 8
// speedup vs baseline: 1.2091x; 1.1135x over previous
#include <cuda_runtime.h>
#include <cuda_bf16.h>
#include <math.h>

#define N_FFT 16000
#define M_HALF 8000
#define BATCH 512
#define IN_DIM 2048
#define NTH 1024

// ---------------- scratch (static __device__, no allocation) ----------------
__device__ int    g_h[2 * IN_DIM];
__device__ float  g_s[2 * IN_DIM];
__device__ float2 g_tw[N_FFT];      // W_N^j = exp(-2*pi*i*j/N)
__device__ int    g_isig[N_FFT];    // natural freq -> scrambled pos (plan 16,10,10,10)
__device__ int    g_isig8[M_HALF];  // natural freq -> scrambled pos (plan 16,10,10,5)
__device__ __align__(16) float g_norm[N_FFT];  // sum |c| -> reciprocal norm

// ---------------- complex helpers ----------------
__device__ __forceinline__ float2 cmul(float2 a, float2 b) {
    return make_float2(a.x * b.x - a.y * b.y, a.x * b.y + a.y * b.x);
}
__device__ __forceinline__ float2 cmulc(float2 a, float2 b) {  // a * conj(b)
    return make_float2(a.x * b.x + a.y * b.y, a.y * b.x - a.x * b.y);
}
__device__ __forceinline__ float2 cadd(float2 a, float2 b) {
    return make_float2(a.x + b.x, a.y + b.y);
}
__device__ __forceinline__ float2 csub(float2 a, float2 b) {
    return make_float2(a.x - b.x, a.y - b.y);
}
__device__ __forceinline__ float2 mul_negi(float2 a) { return make_float2(a.y, -a.x); }
__device__ __forceinline__ float2 mul_posi(float2 a) { return make_float2(-a.y, a.x); }

// W5^j
__constant__ float2 W5c[5] = {
    { 1.0f,                  0.0f                 },
    { 0.30901699437494742f, -0.95105651629515357f },
    {-0.80901699437494742f, -0.58778525229247314f },
    {-0.80901699437494745f,  0.58778525229247312f },
    { 0.30901699437494740f,  0.95105651629515364f }
};
// W10^m, m=0..4
__constant__ float2 W10c[5] = {
    { 1.0f,                  0.0f                 },
    { 0.80901699437494742f, -0.58778525229247312f },
    { 0.30901699437494742f, -0.95105651629515357f },
    {-0.30901699437494742f, -0.95105651629515357f },
    {-0.80901699437494742f, -0.58778525229247312f }
};

#define C_S2 0.70710678118654752440f
#define C16A 0.92387953251128676f
#define C16B 0.38268343236508977f

// ---------------- small DFTs in registers ----------------
#define DFT4F(a,b,c,d,o0,o1,o2,o3) do { \
    float2 _t0 = cadd(a,c), _t1 = csub(a,c); \
    float2 _t2 = cadd(b,d), _t3 = mul_negi(csub(b,d)); \
    o0 = cadd(_t0,_t2); o1 = cadd(_t1,_t3); \
    o2 = csub(_t0,_t2); o3 = csub(_t1,_t3); } while(0)
#define DFT4I(a,b,c,d,o0,o1,o2,o3) do { \
    float2 _t0 = cadd(a,c), _t1 = csub(a,c); \
    float2 _t2 = cadd(b,d), _t3 = mul_posi(csub(b,d)); \
    o0 = cadd(_t0,_t2); o1 = cadd(_t1,_t3); \
    o2 = csub(_t0,_t2); o3 = csub(_t1,_t3); } while(0)

__device__ __forceinline__ void dft16(float2 x[16]) {
    float2 A0[4], A1[4], A2[4], A3[4];
    DFT4F(x[0], x[4], x[8],  x[12], A0[0], A0[1], A0[2], A0[3]);
    DFT4F(x[1], x[5], x[9],  x[13], A1[0], A1[1], A1[2], A1[3]);
    DFT4F(x[2], x[6], x[10], x[14], A2[0], A2[1], A2[2], A2[3]);
    DFT4F(x[3], x[7], x[11], x[15], A3[0], A3[1], A3[2], A3[3]);
    A1[1] = cmul(A1[1], make_float2( C16A, -C16B));
    A1[2] = cmul(A1[2], make_float2( C_S2, -C_S2));
    A1[3] = cmul(A1[3], make_float2( C16B, -C16A));
    A2[1] = cmul(A2[1], make_float2( C_S2, -C_S2));
    A2[2] = mul_negi(A2[2]);
    A2[3] = cmul(A2[3], make_float2(-C_S2, -C_S2));
    A3[1] = cmul(A3[1], make_float2( C16B, -C16A));
    A3[2] = cmul(A3[2], make_float2(-C_S2, -C_S2));
    A3[3] = cmul(A3[3], make_float2(-C16A,  C16B));
#pragma unroll
    for (int m = 0; m < 4; m++)
        DFT4F(A0[m], A1[m], A2[m], A3[m], x[m], x[m+4], x[m+8], x[m+12]);
}

__device__ __forceinline__ void idft16(float2 x[16]) {
    float2 A0[4], A1[4], A2[4], A3[4];
    DFT4I(x[0], x[4], x[8],  x[12], A0[0], A0[1], A0[2], A0[3]);
    DFT4I(x[1], x[5], x[9],  x[13], A1[0], A1[1], A1[2], A1[3]);
    DFT4I(x[2], x[6], x[10], x[14], A2[0], A2[1], A2[2], A2[3]);
    DFT4I(x[3], x[7], x[11], x[15], A3[0], A3[1], A3[2], A3[3]);
    A1[1] = cmul(A1[1], make_float2( C16A,  C16B));
    A1[2] = cmul(A1[2], make_float2( C_S2,  C_S2));
    A1[3] = cmul(A1[3], make_float2( C16B,  C16A));
    A2[1] = cmul(A2[1], make_float2( C_S2,  C_S2));
    A2[2] = mul_posi(A2[2]);
    A2[3] = cmul(A2[3], make_float2(-C_S2,  C_S2));
    A3[1] = cmul(A3[1], make_float2( C16B,  C16A));
    A3[2] = cmul(A3[2], make_float2(-C_S2,  C_S2));
    A3[3] = cmul(A3[3], make_float2(-C16A, -C16B));
#pragma unroll
    for (int m = 0; m < 4; m++)
        DFT4I(A0[m], A1[m], A2[m], A3[m], x[m], x[m+4], x[m+8], x[m+12]);
}

__device__ __forceinline__ void dft5f(float2 a0, float2 a1, float2 a2,
                                      float2 a3, float2 a4, float2 o[5]) {
#pragma unroll
    for (int p = 0; p < 5; p++) {
        float2 acc = a0;
        acc = cadd(acc, cmul(a1, W5c[p % 5]));
        acc = cadd(acc, cmul(a2, W5c[(2*p) % 5]));
        acc = cadd(acc, cmul(a3, W5c[(3*p) % 5]));
        acc = cadd(acc, cmul(a4, W5c[(4*p) % 5]));
        o[p] = acc;
    }
}
__device__ __forceinline__ void dft5i(float2 a0, float2 a1, float2 a2,
                                      float2 a3, float2 a4, float2 o[5]) {
#pragma unroll
    for (int p = 0; p < 5; p++) {
        float2 acc = a0;
        acc = cadd(acc, cmulc(a1, W5c[p % 5]));
        acc = cadd(acc, cmulc(a2, W5c[(2*p) % 5]));
        acc = cadd(acc, cmulc(a3, W5c[(3*p) % 5]));
        acc = cadd(acc, cmulc(a4, W5c[(4*p) % 5]));
        o[p] = acc;
    }
}

__device__ __forceinline__ void dft10(float2 x[10]) {
    float2 B0[5], B1[5];
    dft5f(x[0], x[2], x[4], x[6], x[8], B0);
    dft5f(x[1], x[3], x[5], x[7], x[9], B1);
#pragma unroll
    for (int m = 0; m < 5; m++) {
        float2 t = cmul(B1[m], W10c[m]);
        x[m]     = cadd(B0[m], t);
        x[m + 5] = csub(B0[m], t);
    }
}
__device__ __forceinline__ void idft10(float2 x[10]) {
    float2 B0[5], B1[5];
    dft5i(x[0], x[2], x[4], x[6], x[8], B0);
    dft5i(x[1], x[3], x[5], x[7], x[9], B1);
#pragma unroll
    for (int m = 0; m < 5; m++) {
        float2 t = cmulc(B1[m], W10c[m]);
        x[m]     = cadd(B0[m], t);
        x[m + 5] = csub(B0[m], t);
    }
}

// ---------------- forward FFT stages, 16000 pts (plan: 16,10,10,10) --------
__device__ __forceinline__ void stage16_fwd(float2* sm) {
    const int h = 1000;
    for (int t = threadIdx.x; t < h; t += NTH) {
        float2* b = sm + t;
        float2 x[16];
#pragma unroll
        for (int q = 0; q < 16; q++) x[q] = b[q * h];
        dft16(x);
        float2 T = g_tw[t];
        b[0] = x[0];
        float2 cur = T;
#pragma unroll
        for (int p = 1; p < 16; p++) {
            b[p * h] = cmul(x[p], cur);
            cur = cmul(cur, T);
        }
    }
    __syncthreads();
}

template<int NS, int STRIDE>
__device__ __forceinline__ void stage10_fwd(float2* sm) {
    const int h = NS / 10;
    for (int u = threadIdx.x; u < N_FFT / 10; u += NTH) {
        int blk = u / h, t = u - blk * h;
        float2* b = sm + blk * NS + t;
        float2 x[10];
#pragma unroll
        for (int q = 0; q < 10; q++) x[q] = b[q * h];
        dft10(x);
        if (NS != 10) {
            float2 T = g_tw[t * STRIDE];
            float2 cur = T;
#pragma unroll
            for (int p = 1; p < 10; p++) {
                x[p] = cmul(x[p], cur);
                cur = cmul(cur, T);
            }
        }
#pragma unroll
        for (int p = 0; p < 10; p++) b[p * h] = x[p];
    }
    __syncthreads();
}

// ---------------- inverse FFT stages, 8000 pts (plan: 16,10,10,5) ----------
// Mirrored DIT (reversed stage order, conjugate twiddles), scrambled input ->
// natural order. W_8000^j = W_16000^{2j} -> reuse g_tw with doubled stride.

__device__ __forceinline__ void stage5_inv8(float2* Y) {
    for (int u = threadIdx.x; u < M_HALF / 5; u += NTH) {
        float2* b = Y + u * 5;
        float2 o[5];
        dft5i(b[0], b[1], b[2], b[3], b[4], o);
#pragma unroll
        for (int q = 0; q < 5; q++) b[q] = o[q];
    }
    __syncthreads();
}

template<int NS, int TWIDX>
__device__ __forceinline__ void stage10_inv8(float2* Y) {
    const int h = NS / 10;
    for (int u = threadIdx.x; u < M_HALF / 10; u += NTH) {
        int blk = u / h, t = u - blk * h;
        float2* b = Y + blk * NS + t;
        float2 y[10];
        y[0] = b[0];
        float2 T = g_tw[t * TWIDX];
        float2 cur = T;
#pragma unroll
        for (int p = 1; p < 10; p++) {
            y[p] = cmulc(b[p * h], cur);
            cur = cmul(cur, T);
        }
        idft10(y);
#pragma unroll
        for (int q = 0; q < 10; q++) b[q * h] = y[q];
    }
    __syncthreads();
}

// Final inverse stage (radix-16 over 8000) fused with de-interleave,
// signed-sqrt output (coalesced float2 stores) and column-norm REDG.
__device__ __forceinline__ void stage16_inv_store8(float2* Y, float* dst) {
    const int h = 500;
    float2* dst2 = (float2*)dst;
    for (int t = threadIdx.x; t < h; t += NTH) {
        float2* b = Y + t;
        float2 T = g_tw[2 * t];            // W_8000^t
        float2 y[16];
        y[0] = b[0];
        float2 cur = T;
#pragma unroll
        for (int p = 1; p < 16; p++) {
            y[p] = cmulc(b[p * h], cur);
            cur = cmul(cur, T);
        }
        idft16(y);
#pragma unroll
        for (int q = 0; q < 16; q++) {
            int m = q * 500 + t;           // y[m] = x[2m] + i x[2m+1]
            float c0 = y[q].x, c1 = y[q].y;
            float a0 = fabsf(c0), a1 = fabsf(c1);
            dst2[m] = make_float2(copysignf(sqrtf(a0), c0),
                                  copysignf(sqrtf(a1), c1));
            atomicAdd(&g_norm[2 * m],     a0);   // ss^2 == |c| exactly
            atomicAdd(&g_norm[2 * m + 1], a1);
        }
    }
}

// ------- extract (one block per sketch row) + fused one-time setup ---------
__global__ void k_extract(const float* __restrict__ sk1,
                          const float* __restrict__ sk2) {
    int r = blockIdx.x;

    // fused setup: 4 threads per block handle j = 4r .. 4r+3
    if (threadIdx.x < 4) {
        int j = r * 4 + threadIdx.x;
        if (j < N_FFT) {
            double a = -2.0 * 3.14159265358979323846 * (double)j / (double)N_FFT;
            double sn, cs;
            sincos(a, &sn, &cs);
            g_tw[j] = make_float2((float)cs, (float)sn);
            g_norm[j] = 0.f;
            // isig for plan {16,10,10,10}
            int p0 = j / 1000, rr = j - p0 * 1000;
            int p1 = rr / 100;  rr -= p1 * 100;
            int p2 = rr / 10,  p3 = rr - (rr / 10) * 10;
            g_isig[p0 + 16 * (p1 + 10 * (p2 + 10 * p3))] = j;
            if (j < M_HALF) {
                // isig8 for plan {16,10,10,5}
                int q0 = j / 500, r8 = j - q0 * 500;
                int q1 = r8 / 50; r8 -= q1 * 50;
                int q2 = r8 / 5,  q3 = r8 - q2 * 5;
                g_isig8[q0 + 16 * (q1 + 10 * (q2 + 10 * q3))] = j;
            }
        }
    }

    const float* row = (r < IN_DIM) ? (sk1 + (size_t)r * N_FFT)
                                    : (sk2 + (size_t)(r - IN_DIM) * N_FFT);
    const float4* row4 = (const float4*)row;
    __shared__ int found;
    if (threadIdx.x == 0) found = 0;
    __syncthreads();
    for (int base = 0; base < N_FFT / 4; base += blockDim.x) {
        int j = base + threadIdx.x;
        if (j < N_FFT / 4) {
            float4 v = row4[j];
            if (v.x != 0.f || v.y != 0.f || v.z != 0.f || v.w != 0.f) {
                int   c   = (v.x != 0.f) ? 0 : (v.y != 0.f) ? 1 : (v.z != 0.f) ? 2 : 3;
                float val = (c == 0) ? v.x : (c == 1) ? v.y : (c == 2) ? v.z : v.w;
                g_h[r] = 4 * j + c;
                g_s[r] = val;
                found = 1;
            }
        }
        __syncthreads();
        if (found) break;
    }
}

// ---------------- fused main kernel ----------------
// smem: [0,16000) Z work array, [16000,24000) Y half-spectrum. 192000 bytes.
__global__ void __launch_bounds__(NTH, 1)
k_main(const float* __restrict__ x1, const float* __restrict__ x2,
       float* __restrict__ out) {
    extern __shared__ float2 sm[];
    float2* Y = sm + N_FFT;
    int b = blockIdx.x;

    float4* sm4 = (float4*)sm;
    for (int i = threadIdx.x; i < N_FFT / 2; i += NTH)
        sm4[i] = make_float4(0.f, 0.f, 0.f, 0.f);
    __syncthreads();

    // count-sketch scatter: p1 -> real, p2 -> imag
    const float* r1 = x1 + (size_t)b * IN_DIM;
    const float* r2 = x2 + (size_t)b * IN_DIM;
    for (int k = threadIdx.x; k < IN_DIM; k += NTH) {
        atomicAdd(&sm[g_h[k]].x,          g_s[k]          * r1[k]);
        atomicAdd(&sm[g_h[IN_DIM + k]].y, g_s[IN_DIM + k] * r2[k]);
    }
    __syncthreads();

    // forward 16000-pt FFT of z = p1 + i p2 (scrambled output)
    stage16_fwd(sm);
    stage10_fwd<1000, 16>(sm);
    stage10_fwd<100, 160>(sm);
    stage10_fwd<10, 1600>(sm);

    // Hermitian split + product + irfft half-size packing, all in one pass.
    // Y[k] = (G[k]+G[k+8000]) + i (G[k]-G[k+8000]) e^{+2pi i k/N},
    // G[k+8000] = conj(G[8000-k]).  Writes go to the scrambled order of the
    // 8000-pt inverse plan. Z reads and Y writes live in disjoint smem.
    for (int k = threadIdx.x; k <= 4000; k += NTH) {
        if (k == 0) {
            float2 z0 = sm[g_isig[0]];
            float2 zn = sm[g_isig[M_HALF]];
            float G0 = z0.x * z0.y;         // F1[0]*F2[0]
            float G8 = zn.x * zn.y;         // F1[8000]*F2[8000]
            Y[g_isig8[0]] = make_float2(G0 + G8, G0 - G8);
        } else if (k == 4000) {
            float2 Zk = sm[g_isig[4000]], Zm = sm[g_isig[12000]];
            float2 F1 = make_float2(0.5f*(Zk.x+Zm.x),  0.5f*(Zk.y-Zm.y));
            float2 F2 = make_float2(0.5f*(Zk.y+Zm.y), -0.5f*(Zk.x-Zm.x));
            float2 G = cmul(F1, F2);
            Y[g_isig8[4000]] = make_float2(2.f * G.x, -2.f * G.y);
        } else {
            int mk = M_HALF - k;
            float2 Zk  = sm[g_isig[k]],  Zmk = sm[g_isig[N_FFT - k]];
            float2 Za  = sm[g_isig[mk]], Zb  = sm[g_isig[M_HALF + k]];
            float2 F1 = make_float2(0.5f*(Zk.x+Zmk.x),  0.5f*(Zk.y-Zmk.y));
            float2 F2 = make_float2(0.5f*(Zk.y+Zmk.y), -0.5f*(Zk.x-Zmk.x));
            float2 Gk = cmul(F1, F2);
            float2 H1 = make_float2(0.5f*(Za.x+Zb.x),  0.5f*(Za.y-Zb.y));
            float2 H2 = make_float2(0.5f*(Za.y+Zb.y), -0.5f*(Za.x-Zb.x));
            float2 Gm = cmul(H1, H2);
            float2 W  = g_tw[k];
            float2 cGm = make_float2(Gm.x, -Gm.y);
            float2 cGk = make_float2(Gk.x, -Gk.y);
            // Y[k]
            float2 A1 = cadd(Gk, cGm);
            float2 B1 = cmulc(csub(Gk, cGm), W);           // * e^{+2pi i k/N}
            Y[g_isig8[k]] = cadd(A1, mul_posi(B1));
            // Y[8000-k]  (e^{+2pi i mk/N} = -W)
            float2 A2 = cadd(Gm, cGk);
            float2 t2 = cmul(csub(Gm, cGk), W);
            Y[g_isig8[mk]] = cadd(A2, mul_posi(make_float2(-t2.x, -t2.y)));
        }
    }
    __syncthreads();

    // 8000-pt inverse (natural order out) fused with de-interleave + store
    stage5_inv8(Y);
    stage10_inv8<50, 320>(Y);
    stage10_inv8<500, 32>(Y);
    stage16_inv_store8(Y, out + (size_t)b * N_FFT);
}

// turn accumulated sums into reciprocal norms (in place)
__global__ void k_rnorm() {
    int d = blockIdx.x * blockDim.x + threadIdx.x;
    if (d < N_FFT)
        g_norm[d] = 1.0f / fmaxf(sqrtf(g_norm[d]), 1e-12f);
}

__global__ void k_normalize(float* __restrict__ out) {
    int c4 = blockIdx.x * blockDim.x + threadIdx.x;
    if (c4 >= N_FFT / 4) return;
    int b = blockIdx.y;
    float4 nv = ((const float4*)g_norm)[c4];
    float4* o4 = (float4*)out + (size_t)b * (N_FFT / 4) + c4;
    float4 v = *o4;
    v.x *= nv.x; v.y *= nv.y; v.z *= nv.z; v.w *= nv.w;
    *o4 = v;
}

// ---------------- launch ----------------
extern "C" void kernel_launch(void* const* d_in, const int* in_sizes, int n_in,
                              void* d_out, int out_size) {
    const float* x1  = (const float*)d_in[0];
    const float* x2  = (const float*)d_in[1];
    const float* sk1 = (const float*)d_in[2];
    const float* sk2 = (const float*)d_in[3];
    float* out = (float*)d_out;

    const int smem = (N_FFT + M_HALF) * sizeof(float2);  // 192000 B
    cudaFuncSetAttribute(k_main, cudaFuncAttributeMaxDynamicSharedMemorySize, smem);

    k_extract<<<2 * IN_DIM, 512>>>(sk1, sk2);
    k_main<<<BATCH, NTH, smem>>>(x1, x2, out);
    k_rnorm<<<(N_FFT + 255) / 256, 256>>>();
    dim3 ng((N_FFT / 4 + 255) / 256, BATCH);
    k_normalize<<<ng, 256>>>(out);
}